// round 5
// baseline (speedup 1.0000x reference)
#include <cuda_runtime.h>

#define B_TOT 2048
#define LN    128
#define CDIM  128
#define NH    4
#define HD    32
#define SCALEF 0.17677669529663687f   // 32^-0.5

typedef unsigned long long ull;

// ---------- f32x2 packed helpers (sm_103a) ----------
__device__ __forceinline__ void fma2(ull& d, ull a, ull b) {
    asm("fma.rn.f32x2 %0, %1, %2, %0;" : "+l"(d) : "l"(a), "l"(b));
}
__device__ __forceinline__ ull pk2(float x, float y) {
    ull r; asm("mov.b64 %0, {%1, %2};" : "=l"(r) : "f"(x), "f"(y)); return r;
}
__device__ __forceinline__ float2 up2(ull u) {
    float2 f; asm("mov.b64 {%0, %1}, %2;" : "=f"(f.x), "=f"(f.y) : "l"(u)); return f;
}

// ------------------------- device scratch (no allocs allowed) ---------------
__device__ float g_q [B_TOT*NH*LN*HD];   // [b][h][l][c], q pre-scaled
__device__ float g_k [B_TOT*NH*LN*HD];
__device__ float g_v [B_TOT*NH*LN*HD];
__device__ float g_oh[B_TOT*LN*CDIM];    // [b][l][h*HD+c]

// =============================================================================
// K1: qkv = x @ qkv_w.T + qkv_b. Full x tile in smem, weights double-buffered
// in 32-wide K chunks -> 101KB smem -> 2 CTAs/SM. f32x2 packed inner loop.
// =============================================================================
__global__ __launch_bounds__(256, 2) void qkv_kernel(const float* __restrict__ x,
                                                     const float* __restrict__ w,
                                                     const float* __restrict__ bias) {
    extern __shared__ float sm[];
    float* xT = sm;                 // [128][132]
    float* ws = sm + 128*132;       // [2][32][132]
    const int b  = blockIdx.x;
    const int t  = threadIdx.x;
    const int tx = t & 15, ty = t >> 4;

    const float* xb = x + (size_t)b*LN*CDIM;
    #pragma unroll
    for (int rep = 0; rep < 64; rep++) {
        int idx = rep*256 + t;
        xT[(idx & 127)*132 + (idx >> 7)] = xb[idx];
    }

    for (int cc = 0; cc < 3; cc++) {
        const float* wb = w + cc*128*128;
        // stage K-chunk 0
        #pragma unroll
        for (int rep = 0; rep < 16; rep++) {
            int idx = rep*256 + t;
            int c = idx >> 5, k = idx & 31;
            ws[k*132 + c] = wb[c*128 + k];
        }
        __syncthreads();

        ull acc2[8][4];
        #pragma unroll
        for (int p = 0; p < 8; p++) {
            #pragma unroll
            for (int q2 = 0; q2 < 4; q2++) acc2[p][q2] = 0ull;
        }

        for (int kc = 0; kc < 4; kc++) {
            const float* wcur = ws + (kc & 1)*32*132;
            #pragma unroll
            for (int kk = 0; kk < 32; kk++) {
                int krow = kc*32 + kk;
                float4 xa = *(const float4*)(xT + krow*132 + ty*8);
                float4 xc = *(const float4*)(xT + krow*132 + ty*8 + 4);
                ulonglong2 wa = *(const ulonglong2*)(wcur + kk*132 + tx*8);
                ulonglong2 wc = *(const ulonglong2*)(wcur + kk*132 + tx*8 + 4);
                float xf[8] = {xa.x,xa.y,xa.z,xa.w,xc.x,xc.y,xc.z,xc.w};
                #pragma unroll
                for (int p = 0; p < 8; p++) {
                    ull xp = pk2(xf[p], xf[p]);
                    fma2(acc2[p][0], xp, wa.x);
                    fma2(acc2[p][1], xp, wa.y);
                    fma2(acc2[p][2], xp, wc.x);
                    fma2(acc2[p][3], xp, wc.y);
                }
            }
            if (kc < 3) {
                float* wnext = ws + ((kc + 1) & 1)*32*132;
                int kbase = (kc + 1)*32;
                #pragma unroll
                for (int rep = 0; rep < 16; rep++) {
                    int idx = rep*256 + t;
                    int c = idx >> 5, k = idx & 31;
                    wnext[k*132 + c] = wb[c*128 + kbase + k];
                }
            }
            __syncthreads();
        }

        float* arr = (cc == 0) ? g_q : ((cc == 1) ? g_k : g_v);
        float scl  = (cc == 0) ? SCALEF : 1.0f;
        #pragma unroll
        for (int ri = 0; ri < 8; ri++) {
            int l = ty*8 + ri;
            #pragma unroll
            for (int g = 0; g < 2; g++) {
                int col = tx*8 + g*4;
                int hh = col >> 5, ch = col & 31;
                float2 e0 = up2(acc2[ri][g*2+0]);
                float2 e1 = up2(acc2[ri][g*2+1]);
                float4 v;
                v.x = (e0.x + bias[cc*128 + col + 0]) * scl;
                v.y = (e0.y + bias[cc*128 + col + 1]) * scl;
                v.z = (e1.x + bias[cc*128 + col + 2]) * scl;
                v.w = (e1.y + bias[cc*128 + col + 3]) * scl;
                *(float4*)(arr + (((size_t)b*NH + hh)*LN + l)*HD + ch) = v;
            }
        }
    }
}

// =============================================================================
// K2: fused attention per (b, h). 512 threads: jq = tid>>7 (j quarter),
// i = tid&127. Logits live in registers (att[32]); mask loaded straight from
// global (contiguous 128B per thread). f32x2 packed dot products everywhere.
// =============================================================================
__global__ __launch_bounds__(512, 1) void attn_kernel(const float* __restrict__ mask,
                                                      const float* __restrict__ rpe) {
    extern __shared__ float sm[];
    float* k_s  = sm;                   // [128][32]
    float* v_s  = k_s + 4096;           // [128][32]
    float* tq   = v_s + 4096;           // [225][36] (scaled by SCALEF)
    float* tk   = tq  + 8100;           // [225][36]
    float* tv   = tk  + 8100;           // [225][36]
    float* buf0 = tv  + 8100;           // [128][36]
    float* buf1 = buf0 + 4608;          // [128][36]
    float* redm = buf1 + 4608;          // [512]
    float* reds = redm + 512;           // [512]

    const int b = blockIdx.x, h = blockIdx.y;
    const int t  = threadIdx.x;
    const int i  = t & 127;
    const int jq = t >> 7;              // 0..3, owns j in [jq*32, jq*32+32)

    // ---- stage k, v (128*32 floats = 1024 float4; 2 reps x 512 threads) ----
    {
        const float4* kg = (const float4*)(g_k + (((size_t)b*NH + h)*LN)*HD);
        const float4* vg = (const float4*)(g_v + (((size_t)b*NH + h)*LN)*HD);
        float4* k4 = (float4*)k_s;
        float4* v4 = (float4*)v_s;
        #pragma unroll
        for (int r = 0; r < 2; r++) { k4[r*512 + t] = kg[r*512 + t];
                                      v4[r*512 + t] = vg[r*512 + t]; }
    }
    // ---- stage rpe tables for this head (225 x 96 -> three 225x36-padded) ----
    for (int idx = t; idx < 225*96; idx += 512) {
        int tt = idx / 96;
        int u  = idx - tt*96;
        float val = rpe[tt*384 + h*96 + u];
        if      (u < 32) tq[tt*36 + u]      = val * SCALEF;
        else if (u < 64) tk[tt*36 + u - 32] = val;
        else             tv[tt*36 + u - 64] = val;
    }
    // ---- q row into packed registers ----
    ull qv[16];
    {
        const ulonglong2* qg = (const ulonglong2*)(g_q + (((size_t)b*NH + h)*LN + i)*HD);
        #pragma unroll
        for (int u = 0; u < 8; u++) { ulonglong2 z = qg[u]; qv[2*u] = z.x; qv[2*u+1] = z.y; }
    }
    // ---- att init from mask (contiguous 128B per thread, full sectors) ----
    float att[32];
    {
        const float4* mp = (const float4*)(mask + (size_t)(b & 127)*LN*LN + i*LN + jq*32);
        #pragma unroll
        for (int u = 0; u < 8; u++) {
            float4 m4 = mp[u];
            att[u*4+0] = m4.x; att[u*4+1] = m4.y; att[u*4+2] = m4.z; att[u*4+3] = m4.w;
        }
    }
    __syncthreads();

    const int hi = i >> 4;
    const int wi = (i >> 1) & 7;

    // ---- logits ----
    #pragma unroll
    for (int jj = 0; jj < 16; jj++) {
        int pj = jq*16 + jj;
        int ridx = (hi - (pj >> 3) + 7)*15 + (wi - (pj & 7) + 7);
        const ulonglong2* k0p = (const ulonglong2*)(k_s + pj*2*HD);
        const ulonglong2* k1p = k0p + 8;
        const ulonglong2* tkp = (const ulonglong2*)(tk + ridx*36);
        const ulonglong2* tqp = (const ulonglong2*)(tq + ridx*36);
        ull qk0 = 0, qk1 = 0, qr = 0, kr0 = 0, kr1 = 0;
        #pragma unroll
        for (int u = 0; u < 8; u++) {
            ulonglong2 kv0 = k0p[u], kv1 = k1p[u], tkv = tkp[u], tqv = tqp[u];
            ull q0 = qv[2*u], q1 = qv[2*u+1];
            fma2(qk0, q0, kv0.x); fma2(qk0, q1, kv0.y);
            fma2(qk1, q0, kv1.x); fma2(qk1, q1, kv1.y);
            fma2(qr,  q0, tkv.x); fma2(qr,  q1, tkv.y);
            fma2(kr0, kv0.x, tqv.x); fma2(kr0, kv0.y, tqv.y);
            fma2(kr1, kv1.x, tqv.x); fma2(kr1, kv1.y, tqv.y);
        }
        float2 f0 = up2(qk0), f1 = up2(qk1), fr = up2(qr), g0 = up2(kr0), g1 = up2(kr1);
        float qrs = fr.x + fr.y;
        att[2*jj]   += f0.x + f0.y + qrs + g0.x + g0.y;
        att[2*jj+1] += f1.x + f1.y + qrs + g1.x + g1.y;
    }

    // ---- softmax over full row (4 jq threads share row i) ----
    float m = att[0];
    #pragma unroll
    for (int u = 1; u < 32; u++) m = fmaxf(m, att[u]);
    redm[jq*128 + i] = m;
    __syncthreads();
    m = fmaxf(fmaxf(redm[i], redm[128 + i]), fmaxf(redm[256 + i], redm[384 + i]));
    float ls = 0.f;
    #pragma unroll
    for (int u = 0; u < 32; u++) { float e = __expf(att[u] - m); att[u] = e; ls += e; }
    reds[jq*128 + i] = ls;
    __syncthreads();
    float rinv = 1.0f / (reds[i] + reds[128 + i] + reds[256 + i] + reds[384 + i]);

    // ---- output: acc2 packed over c ----
    ull acc2[16];
    #pragma unroll
    for (int u = 0; u < 16; u++) acc2[u] = 0ull;

    #pragma unroll
    for (int jj = 0; jj < 16; jj++) {
        int pj = jq*16 + jj;
        int ridx = (hi - (pj >> 3) + 7)*15 + (wi - (pj & 7) + 7);
        const ulonglong2* v0p = (const ulonglong2*)(v_s + pj*2*HD);
        const ulonglong2* v1p = v0p + 8;
        const ulonglong2* tvp = (const ulonglong2*)(tv + ridx*36);
        float a0 = att[2*jj], a1 = att[2*jj+1];
        ull ap0 = pk2(a0, a0), ap1 = pk2(a1, a1), ap2 = pk2(a0 + a1, a0 + a1);
        #pragma unroll
        for (int u = 0; u < 8; u++) {
            ulonglong2 vv0 = v0p[u], vv1 = v1p[u], tvv = tvp[u];
            fma2(acc2[2*u],   ap0, vv0.x); fma2(acc2[2*u+1], ap0, vv0.y);
            fma2(acc2[2*u],   ap1, vv1.x); fma2(acc2[2*u+1], ap1, vv1.y);
            fma2(acc2[2*u],   ap2, tvv.x); fma2(acc2[2*u+1], ap2, tvv.y);
        }
    }

    float o[32];
    #pragma unroll
    for (int u = 0; u < 16; u++) {
        float2 f = up2(acc2[u]);
        o[2*u] = f.x * rinv; o[2*u+1] = f.y * rinv;
    }

    // ---- reduce 4 partial sums per row, store to g_oh ----
    if (jq == 2) {
        for (int c = 0; c < 8; c++) *(float4*)(buf0 + i*36 + c*4) = *(float4*)(o + c*4);
    }
    if (jq == 3) {
        for (int c = 0; c < 8; c++) *(float4*)(buf1 + i*36 + c*4) = *(float4*)(o + c*4);
    }
    __syncthreads();
    if (jq == 0) {
        for (int c = 0; c < 32; c++) o[c] += buf0[i*36 + c];
    }
    if (jq == 1) {
        for (int c = 0; c < 32; c++) o[c] += buf1[i*36 + c];
    }
    __syncthreads();
    if (jq == 1) {
        for (int c = 0; c < 8; c++) *(float4*)(buf0 + i*36 + c*4) = *(float4*)(o + c*4);
    }
    __syncthreads();
    if (jq == 0) {
        float* dst = g_oh + ((size_t)b*LN + i)*CDIM + h*HD;
        #pragma unroll
        for (int c = 0; c < 8; c++) {
            float4 v;
            v.x = o[c*4+0] + buf0[i*36 + c*4+0];
            v.y = o[c*4+1] + buf0[i*36 + c*4+1];
            v.z = o[c*4+2] + buf0[i*36 + c*4+2];
            v.w = o[c*4+3] + buf0[i*36 + c*4+3];
            *(float4*)dst = v; dst += 4;
        }
    }
}

// =============================================================================
// K3: out = oh @ proj_w.T + proj_b (same scheme as K1, single weight block)
// =============================================================================
__global__ __launch_bounds__(256, 2) void proj_kernel(const float* __restrict__ w,
                                                      const float* __restrict__ bias,
                                                      float* __restrict__ out) {
    extern __shared__ float sm[];
    float* xT = sm;                 // [128][132]
    float* ws = sm + 128*132;       // [2][32][132]
    const int b  = blockIdx.x;
    const int t  = threadIdx.x;
    const int tx = t & 15, ty = t >> 4;

    const float* xb = g_oh + (size_t)b*LN*CDIM;
    #pragma unroll
    for (int rep = 0; rep < 64; rep++) {
        int idx = rep*256 + t;
        xT[(idx & 127)*132 + (idx >> 7)] = xb[idx];
    }
    #pragma unroll
    for (int rep = 0; rep < 16; rep++) {
        int idx = rep*256 + t;
        int c = idx >> 5, k = idx & 31;
        ws[k*132 + c] = w[c*128 + k];
    }
    __syncthreads();

    ull acc2[8][4];
    #pragma unroll
    for (int p = 0; p < 8; p++) {
        #pragma unroll
        for (int q2 = 0; q2 < 4; q2++) acc2[p][q2] = 0ull;
    }

    for (int kc = 0; kc < 4; kc++) {
        const float* wcur = ws + (kc & 1)*32*132;
        #pragma unroll
        for (int kk = 0; kk < 32; kk++) {
            int krow = kc*32 + kk;
            float4 xa = *(const float4*)(xT + krow*132 + ty*8);
            float4 xc = *(const float4*)(xT + krow*132 + ty*8 + 4);
            ulonglong2 wa = *(const ulonglong2*)(wcur + kk*132 + tx*8);
            ulonglong2 wc = *(const ulonglong2*)(wcur + kk*132 + tx*8 + 4);
            float xf[8] = {xa.x,xa.y,xa.z,xa.w,xc.x,xc.y,xc.z,xc.w};
            #pragma unroll
            for (int p = 0; p < 8; p++) {
                ull xp = pk2(xf[p], xf[p]);
                fma2(acc2[p][0], xp, wa.x);
                fma2(acc2[p][1], xp, wa.y);
                fma2(acc2[p][2], xp, wc.x);
                fma2(acc2[p][3], xp, wc.y);
            }
        }
        if (kc < 3) {
            float* wnext = ws + ((kc + 1) & 1)*32*132;
            int kbase = (kc + 1)*32;
            #pragma unroll
            for (int rep = 0; rep < 16; rep++) {
                int idx = rep*256 + t;
                int c = idx >> 5, k = idx & 31;
                wnext[k*132 + c] = w[c*128 + kbase + k];
            }
        }
        __syncthreads();
    }

    #pragma unroll
    for (int ri = 0; ri < 8; ri++) {
        int l = ty*8 + ri;
        #pragma unroll
        for (int g = 0; g < 2; g++) {
            int col = tx*8 + g*4;
            float2 e0 = up2(acc2[ri][g*2+0]);
            float2 e1 = up2(acc2[ri][g*2+1]);
            float4 v;
            v.x = e0.x + bias[col + 0];
            v.y = e0.y + bias[col + 1];
            v.z = e1.x + bias[col + 2];
            v.w = e1.y + bias[col + 3];
            *(float4*)(out + ((size_t)b*LN + l)*CDIM + col) = v;
        }
    }
}

// =============================================================================
extern "C" void kernel_launch(void* const* d_in, const int* in_sizes, int n_in,
                              void* d_out, int out_size) {
    const float* x        = (const float*)d_in[0];
    const float* attn_msk = (const float*)d_in[1];
    const float* qkv_w    = (const float*)d_in[2];
    const float* qkv_b    = (const float*)d_in[3];
    const float* rpe      = (const float*)d_in[4];
    const float* proj_w   = (const float*)d_in[5];
    const float* proj_b   = (const float*)d_in[6];
    float* out = (float*)d_out;

    const int smem_gemm = (128*132 + 2*32*132)*sizeof(float);                 // 101376
    const int smem_attn = (4096*2 + 3*8100 + 2*4608 + 1024)*sizeof(float);    // 170928

    cudaFuncSetAttribute(qkv_kernel,  cudaFuncAttributeMaxDynamicSharedMemorySize, smem_gemm);
    cudaFuncSetAttribute(attn_kernel, cudaFuncAttributeMaxDynamicSharedMemorySize, smem_attn);
    cudaFuncSetAttribute(proj_kernel, cudaFuncAttributeMaxDynamicSharedMemorySize, smem_gemm);

    qkv_kernel <<<B_TOT, 256, smem_gemm>>>(x, qkv_w, qkv_b);
    attn_kernel<<<dim3(B_TOT, NH), 512, smem_attn>>>(attn_msk, rpe);
    proj_kernel<<<B_TOT, 256, smem_gemm>>>(proj_w, proj_b, out);
}

// round 8
// speedup vs baseline: 1.2601x; 1.2601x over previous
#include <cuda_runtime.h>
#include <cstdint>

#define B_TOT 2048
#define LN    128
#define CDIM  128
#define NH    4
#define HD    32
#define SCALEF 0.17677669529663687f   // 32^-0.5

typedef unsigned long long ull;

// ---------- f32x2 packed helpers (sm_103a) ----------
__device__ __forceinline__ void fma2(ull& d, ull a, ull b) {
    asm("fma.rn.f32x2 %0, %1, %2, %0;" : "+l"(d) : "l"(a), "l"(b));
}
__device__ __forceinline__ ull pk2(float x, float y) {
    ull r; asm("mov.b64 %0, {%1, %2};" : "=l"(r) : "f"(x), "f"(y)); return r;
}
__device__ __forceinline__ float2 up2(ull u) {
    float2 f; asm("mov.b64 {%0, %1}, %2;" : "=f"(f.x), "=f"(f.y) : "l"(u)); return f;
}

// ---------- tf32 warp MMA helpers (sm_80 baseline -> legal at compute_103) ---
__device__ __forceinline__ float tf32r(float f) {
    uint32_t u; asm("cvt.rna.tf32.f32 %0, %1;" : "=r"(u) : "f"(f));
    return __uint_as_float(u);
}
__device__ __forceinline__ void mma8(float* c, const float* a, float b0, float b1) {
    asm volatile(
        "mma.sync.aligned.m16n8k8.row.col.f32.tf32.tf32.f32 "
        "{%0,%1,%2,%3}, {%4,%5,%6,%7}, {%8,%9}, {%0,%1,%2,%3};"
        : "+f"(c[0]), "+f"(c[1]), "+f"(c[2]), "+f"(c[3])
        : "r"(__float_as_uint(a[0])), "r"(__float_as_uint(a[1])),
          "r"(__float_as_uint(a[2])), "r"(__float_as_uint(a[3])),
          "r"(__float_as_uint(b0)),  "r"(__float_as_uint(b1)));
}

// stage a 128x128 fp32 tile (row-major contiguous) into smem stride-132, tf32-rounded
__device__ __forceinline__ void stage128(float* dst, const float* __restrict__ src, int t) {
    const float4* g = (const float4*)src;
    #pragma unroll
    for (int r = 0; r < 16; r++) {
        int idx = r * 256 + t;            // 4096 float4 total
        float4 v = g[idx];
        int row = idx >> 5, col = (idx & 31) * 4;
        float* d = dst + row * 132 + col;
        d[0] = tf32r(v.x); d[1] = tf32r(v.y); d[2] = tf32r(v.z); d[3] = tf32r(v.w);
    }
}

// ------------------------- device scratch (no allocs allowed) ---------------
__device__ float g_q [B_TOT*NH*LN*HD];   // [b][h][l][c], q pre-scaled
__device__ float g_k [B_TOT*NH*LN*HD];
__device__ float g_v [B_TOT*NH*LN*HD];
__device__ float g_oh[B_TOT*LN*CDIM];    // [b][l][h*HD+c]

// =============================================================================
// K1 (warp-MMA tf32): qkv = x @ qkv_w.T + qkv_b, per-window 128x384x128.
// 8 warps: warp = (m-strip of 32 rows [wid&3], n-half of 64 cols [wid>>2]).
// A fragments register-resident; B double-buffered in smem.
// =============================================================================
__global__ __launch_bounds__(256) void qkv_mma(const float* __restrict__ x,
                                               const float* __restrict__ w,
                                               const float* __restrict__ bias) {
    extern __shared__ float sm[];
    float* xs = sm;                       // [128][132]
    float* ws = sm + 128*132;             // [2][128][132]
    float* bs = sm + 3*128*132;           // [384]
    const int b = blockIdx.x, t = threadIdx.x;
    const int wid = t >> 5, lane = t & 31;
    const int gr = lane >> 2, tc = lane & 3;
    const int mrow = (wid & 3) * 32;
    const int n0b  = (wid >> 2) * 64;

    stage128(xs, x + (size_t)b * 16384, t);
    stage128(ws,             w,         t);
    stage128(ws + 128*132,   w + 16384, t);
    for (int idx = t; idx < 384; idx += 256) bs[idx] = bias[idx];
    __syncthreads();

    // A fragments: 2 m-tiles x 16 k-steps x 4 regs
    float a[2][16][4];
    #pragma unroll
    for (int mt = 0; mt < 2; mt++) {
        int r0 = mrow + mt * 16 + gr;
        #pragma unroll
        for (int ks = 0; ks < 16; ks++) {
            a[mt][ks][0] = xs[ r0      * 132 + ks*8 + tc];
            a[mt][ks][1] = xs[(r0 + 8) * 132 + ks*8 + tc];
            a[mt][ks][2] = xs[ r0      * 132 + ks*8 + tc + 4];
            a[mt][ks][3] = xs[(r0 + 8) * 132 + ks*8 + tc + 4];
        }
    }

    for (int cc = 0; cc < 3; cc++) {
        if (cc == 2) {                    // buffer0 free after chunk0 done by all warps
            __syncthreads();
            stage128(ws, w + 32768, t);
            __syncthreads();
        }
        const float* wc = ws + (cc & 1) * (128*132);
        float* arr = (cc == 0) ? g_q : ((cc == 1) ? g_k : g_v);
        const float scl = (cc == 0) ? SCALEF : 1.0f;
        #pragma unroll
        for (int nt = 0; nt < 8; nt++) {
            int n0 = n0b + nt * 8;
            float c0[4] = {0.f,0.f,0.f,0.f};
            float c1[4] = {0.f,0.f,0.f,0.f};
            #pragma unroll
            for (int ks = 0; ks < 16; ks++) {
                float b0 = wc[(n0 + gr) * 132 + ks*8 + tc];
                float b1 = wc[(n0 + gr) * 132 + ks*8 + tc + 4];
                mma8(c0, a[0][ks], b0, b1);
                mma8(c1, a[1][ks], b0, b1);
            }
            int cch = n0 + 2 * tc;        // col within chunk [0,128)
            float bb0 = bs[cc*128 + cch], bb1 = bs[cc*128 + cch + 1];
            int h = cch >> 5, ch = cch & 31;
            float* base = arr + (((size_t)b * NH + h) * LN) * HD + ch;
            #pragma unroll
            for (int mt = 0; mt < 2; mt++) {
                float* cr = mt ? c1 : c0;
                int r0 = mrow + mt * 16 + gr;
                float2 v0 = make_float2((cr[0] + bb0) * scl, (cr[1] + bb1) * scl);
                float2 v1 = make_float2((cr[2] + bb0) * scl, (cr[3] + bb1) * scl);
                *(float2*)(base +  r0      * HD) = v0;
                *(float2*)(base + (r0 + 8) * HD) = v1;
            }
        }
    }
}

// =============================================================================
// K2: fused attention per (b, h) — unchanged from passing R5 kernel.
// =============================================================================
__global__ __launch_bounds__(512, 1) void attn_kernel(const float* __restrict__ mask,
                                                      const float* __restrict__ rpe) {
    extern __shared__ float sm[];
    float* k_s  = sm;                   // [128][32]
    float* v_s  = k_s + 4096;           // [128][32]
    float* tq   = v_s + 4096;           // [225][36] (scaled by SCALEF)
    float* tk   = tq  + 8100;           // [225][36]
    float* tv   = tk  + 8100;           // [225][36]
    float* buf0 = tv  + 8100;           // [128][36]
    float* buf1 = buf0 + 4608;          // [128][36]
    float* redm = buf1 + 4608;          // [512]
    float* reds = redm + 512;           // [512]

    const int b = blockIdx.x, h = blockIdx.y;
    const int t  = threadIdx.x;
    const int i  = t & 127;
    const int jq = t >> 7;              // 0..3, owns j in [jq*32, jq*32+32)

    {
        const float4* kg = (const float4*)(g_k + (((size_t)b*NH + h)*LN)*HD);
        const float4* vg = (const float4*)(g_v + (((size_t)b*NH + h)*LN)*HD);
        float4* k4 = (float4*)k_s;
        float4* v4 = (float4*)v_s;
        #pragma unroll
        for (int r = 0; r < 2; r++) { k4[r*512 + t] = kg[r*512 + t];
                                      v4[r*512 + t] = vg[r*512 + t]; }
    }
    for (int idx = t; idx < 225*96; idx += 512) {
        int tt = idx / 96;
        int u  = idx - tt*96;
        float val = rpe[tt*384 + h*96 + u];
        if      (u < 32) tq[tt*36 + u]      = val * SCALEF;
        else if (u < 64) tk[tt*36 + u - 32] = val;
        else             tv[tt*36 + u - 64] = val;
    }
    ull qv[16];
    {
        const ulonglong2* qg = (const ulonglong2*)(g_q + (((size_t)b*NH + h)*LN + i)*HD);
        #pragma unroll
        for (int u = 0; u < 8; u++) { ulonglong2 z = qg[u]; qv[2*u] = z.x; qv[2*u+1] = z.y; }
    }
    float att[32];
    {
        const float4* mp = (const float4*)(mask + (size_t)(b & 127)*LN*LN + i*LN + jq*32);
        #pragma unroll
        for (int u = 0; u < 8; u++) {
            float4 m4 = mp[u];
            att[u*4+0] = m4.x; att[u*4+1] = m4.y; att[u*4+2] = m4.z; att[u*4+3] = m4.w;
        }
    }
    __syncthreads();

    const int hi = i >> 4;
    const int wi = (i >> 1) & 7;

    #pragma unroll
    for (int jj = 0; jj < 16; jj++) {
        int pj = jq*16 + jj;
        int ridx = (hi - (pj >> 3) + 7)*15 + (wi - (pj & 7) + 7);
        const ulonglong2* k0p = (const ulonglong2*)(k_s + pj*2*HD);
        const ulonglong2* k1p = k0p + 8;
        const ulonglong2* tkp = (const ulonglong2*)(tk + ridx*36);
        const ulonglong2* tqp = (const ulonglong2*)(tq + ridx*36);
        ull qk0 = 0, qk1 = 0, qr = 0, kr0 = 0, kr1 = 0;
        #pragma unroll
        for (int u = 0; u < 8; u++) {
            ulonglong2 kv0 = k0p[u], kv1 = k1p[u], tkv = tkp[u], tqv = tqp[u];
            ull q0 = qv[2*u], q1 = qv[2*u+1];
            fma2(qk0, q0, kv0.x); fma2(qk0, q1, kv0.y);
            fma2(qk1, q0, kv1.x); fma2(qk1, q1, kv1.y);
            fma2(qr,  q0, tkv.x); fma2(qr,  q1, tkv.y);
            fma2(kr0, kv0.x, tqv.x); fma2(kr0, kv0.y, tqv.y);
            fma2(kr1, kv1.x, tqv.x); fma2(kr1, kv1.y, tqv.y);
        }
        float2 f0 = up2(qk0), f1 = up2(qk1), fr = up2(qr), g0 = up2(kr0), g1 = up2(kr1);
        float qrs = fr.x + fr.y;
        att[2*jj]   += f0.x + f0.y + qrs + g0.x + g0.y;
        att[2*jj+1] += f1.x + f1.y + qrs + g1.x + g1.y;
    }

    float m = att[0];
    #pragma unroll
    for (int u = 1; u < 32; u++) m = fmaxf(m, att[u]);
    redm[jq*128 + i] = m;
    __syncthreads();
    m = fmaxf(fmaxf(redm[i], redm[128 + i]), fmaxf(redm[256 + i], redm[384 + i]));
    float ls = 0.f;
    #pragma unroll
    for (int u = 0; u < 32; u++) { float e = __expf(att[u] - m); att[u] = e; ls += e; }
    reds[jq*128 + i] = ls;
    __syncthreads();
    float rinv = 1.0f / (reds[i] + reds[128 + i] + reds[256 + i] + reds[384 + i]);

    ull acc2[16];
    #pragma unroll
    for (int u = 0; u < 16; u++) acc2[u] = 0ull;

    #pragma unroll
    for (int jj = 0; jj < 16; jj++) {
        int pj = jq*16 + jj;
        int ridx = (hi - (pj >> 3) + 7)*15 + (wi - (pj & 7) + 7);
        const ulonglong2* v0p = (const ulonglong2*)(v_s + pj*2*HD);
        const ulonglong2* v1p = v0p + 8;
        const ulonglong2* tvp = (const ulonglong2*)(tv + ridx*36);
        float a0 = att[2*jj], a1 = att[2*jj+1];
        ull ap0 = pk2(a0, a0), ap1 = pk2(a1, a1), ap2 = pk2(a0 + a1, a0 + a1);
        #pragma unroll
        for (int u = 0; u < 8; u++) {
            ulonglong2 vv0 = v0p[u], vv1 = v1p[u], tvv = tvp[u];
            fma2(acc2[2*u],   ap0, vv0.x); fma2(acc2[2*u+1], ap0, vv0.y);
            fma2(acc2[2*u],   ap1, vv1.x); fma2(acc2[2*u+1], ap1, vv1.y);
            fma2(acc2[2*u],   ap2, tvv.x); fma2(acc2[2*u+1], ap2, tvv.y);
        }
    }

    float o[32];
    #pragma unroll
    for (int u = 0; u < 16; u++) {
        float2 f = up2(acc2[u]);
        o[2*u] = f.x * rinv; o[2*u+1] = f.y * rinv;
    }

    if (jq == 2) {
        for (int c = 0; c < 8; c++) *(float4*)(buf0 + i*36 + c*4) = *(float4*)(o + c*4);
    }
    if (jq == 3) {
        for (int c = 0; c < 8; c++) *(float4*)(buf1 + i*36 + c*4) = *(float4*)(o + c*4);
    }
    __syncthreads();
    if (jq == 0) {
        for (int c = 0; c < 32; c++) o[c] += buf0[i*36 + c];
    }
    if (jq == 1) {
        for (int c = 0; c < 32; c++) o[c] += buf1[i*36 + c];
    }
    __syncthreads();
    if (jq == 1) {
        for (int c = 0; c < 8; c++) *(float4*)(buf0 + i*36 + c*4) = *(float4*)(o + c*4);
    }
    __syncthreads();
    if (jq == 0) {
        float* dst = g_oh + ((size_t)b*LN + i)*CDIM + h*HD;
        #pragma unroll
        for (int c = 0; c < 8; c++) {
            float4 v;
            v.x = o[c*4+0] + buf0[i*36 + c*4+0];
            v.y = o[c*4+1] + buf0[i*36 + c*4+1];
            v.z = o[c*4+2] + buf0[i*36 + c*4+2];
            v.w = o[c*4+3] + buf0[i*36 + c*4+3];
            *(float4*)dst = v; dst += 4;
        }
    }
}

// =============================================================================
// K3 (warp-MMA tf32): out = oh @ proj_w.T + proj_b, 128x128x128 per window.
// =============================================================================
__global__ __launch_bounds__(256) void proj_mma(const float* __restrict__ w,
                                                const float* __restrict__ bias,
                                                float* __restrict__ out) {
    extern __shared__ float sm[];
    float* xs = sm;                       // [128][132]
    float* ws = sm + 128*132;             // [128][132]
    float* bs = sm + 2*128*132;           // [128]
    const int b = blockIdx.x, t = threadIdx.x;
    const int wid = t >> 5, lane = t & 31;
    const int gr = lane >> 2, tc = lane & 3;
    const int mrow = (wid & 3) * 32;
    const int n0b  = (wid >> 2) * 64;

    stage128(xs, g_oh + (size_t)b * 16384, t);
    stage128(ws, w, t);
    if (t < 128) bs[t] = bias[t];
    __syncthreads();

    float a[2][16][4];
    #pragma unroll
    for (int mt = 0; mt < 2; mt++) {
        int r0 = mrow + mt * 16 + gr;
        #pragma unroll
        for (int ks = 0; ks < 16; ks++) {
            a[mt][ks][0] = xs[ r0      * 132 + ks*8 + tc];
            a[mt][ks][1] = xs[(r0 + 8) * 132 + ks*8 + tc];
            a[mt][ks][2] = xs[ r0      * 132 + ks*8 + tc + 4];
            a[mt][ks][3] = xs[(r0 + 8) * 132 + ks*8 + tc + 4];
        }
    }

    #pragma unroll
    for (int nt = 0; nt < 8; nt++) {
        int n0 = n0b + nt * 8;
        float c0[4] = {0.f,0.f,0.f,0.f};
        float c1[4] = {0.f,0.f,0.f,0.f};
        #pragma unroll
        for (int ks = 0; ks < 16; ks++) {
            float b0 = ws[(n0 + gr) * 132 + ks*8 + tc];
            float b1 = ws[(n0 + gr) * 132 + ks*8 + tc + 4];
            mma8(c0, a[0][ks], b0, b1);
            mma8(c1, a[1][ks], b0, b1);
        }
        int cch = n0 + 2 * tc;
        float bb0 = bs[cch], bb1 = bs[cch + 1];
        float* base = out + ((size_t)b * LN) * CDIM + cch;
        #pragma unroll
        for (int mt = 0; mt < 2; mt++) {
            float* cr = mt ? c1 : c0;
            int r0 = mrow + mt * 16 + gr;
            *(float2*)(base +  r0      * CDIM) = make_float2(cr[0] + bb0, cr[1] + bb1);
            *(float2*)(base + (r0 + 8) * CDIM) = make_float2(cr[2] + bb0, cr[3] + bb1);
        }
    }
}

// =============================================================================
extern "C" void kernel_launch(void* const* d_in, const int* in_sizes, int n_in,
                              void* d_out, int out_size) {
    const float* x        = (const float*)d_in[0];
    const float* attn_msk = (const float*)d_in[1];
    const float* qkv_w    = (const float*)d_in[2];
    const float* qkv_b    = (const float*)d_in[3];
    const float* rpe      = (const float*)d_in[4];
    const float* proj_w   = (const float*)d_in[5];
    const float* proj_b   = (const float*)d_in[6];
    float* out = (float*)d_out;

    const int smem_k1   = (3*128*132 + 384) * sizeof(float);                  // 204288
    const int smem_attn = (4096*2 + 3*8100 + 2*4608 + 1024) * sizeof(float);  // 170928
    const int smem_k3   = (2*128*132 + 128) * sizeof(float);                  // 135680

    cudaFuncSetAttribute(qkv_mma,     cudaFuncAttributeMaxDynamicSharedMemorySize, smem_k1);
    cudaFuncSetAttribute(attn_kernel, cudaFuncAttributeMaxDynamicSharedMemorySize, smem_attn);
    cudaFuncSetAttribute(proj_mma,    cudaFuncAttributeMaxDynamicSharedMemorySize, smem_k3);

    qkv_mma <<<B_TOT, 256, smem_k1>>>(x, qkv_w, qkv_b);
    attn_kernel<<<dim3(B_TOT, NH), 512, smem_attn>>>(attn_msk, rpe);
    proj_mma<<<B_TOT, 256, smem_k3>>>(proj_w, proj_b, out);
}